// round 3
// baseline (speedup 1.0000x reference)
#include <cuda_runtime.h>
#include <cstdint>

#define B_ 8
#define V_ 8192
#define N_ 2048
#define C_ 128

typedef unsigned long long ull;

// ---------- f32x2 helpers (sm_100+ packed fp32: SASS FFMA2/FADD2/FMUL2) ----------
__device__ __forceinline__ ull pk2(float lo, float hi) {
    ull r; asm("mov.b64 %0, {%1, %2};" : "=l"(r) : "f"(lo), "f"(hi)); return r;
}
__device__ __forceinline__ void upk2(ull v, float& lo, float& hi) {
    asm("mov.b64 {%0, %1}, %2;" : "=f"(lo), "=f"(hi) : "l"(v));
}
__device__ __forceinline__ ull ffma2(ull a, ull b, ull c) {
    ull d; asm("fma.rn.f32x2 %0, %1, %2, %3;" : "=l"(d) : "l"(a), "l"(b), "l"(c)); return d;
}

// ---------- device scratch ----------
__device__ float g_buf[B_ * N_];          // g[b,n] = MLP(processed[b,n])
__device__ ull   W1p[64 * 128];           // packed W1: {W1[2c2][d], W1[2c2+1][d]}
__device__ float cand_val[4 * B_ * V_];   // per n-chunk exact best d2
__device__ int   cand_idx[4 * B_ * V_];   // per n-chunk best index (global n)

// =====================================================================
// Kernel P: pack W1 row pairs for f32x2 consumption.
// =====================================================================
__global__ void kernelP(const float* __restrict__ W1) {
    int i = blockIdx.x * 256 + threadIdx.x;     // 8192 entries
    int c2 = i >> 7, d = i & 127;
    W1p[i] = pk2(W1[(2 * c2) * C_ + d], W1[(2 * c2 + 1) * C_ + d]);
}

// =====================================================================
// Kernel A: g table. 256 blocks x 64 rows, 512 threads.
// Thread tile 4 rows x 4 outputs -> acc = 16 u64 = 32 regs (no spill
// under the 128-reg cap at 512 threads; old 4x8 tile spilled).
// tr = warp id -> x smem loads are warp-uniform broadcasts.
// =====================================================================
__global__ void __launch_bounds__(512, 1)
kernelA(const float* __restrict__ processed,
        const float* __restrict__ b1,
        const float* __restrict__ W2,
        const float* __restrict__ b2) {
    extern __shared__ float Xs[];            // [64][128] = 32KB
    __shared__ float red[64][33];

    const int t = threadIdx.x;
    const int rowBase = blockIdx.x * 64;

    // Load 64 rows of processed into smem (float4 contiguous).
    const float4* src = (const float4*)(processed + (size_t)rowBase * C_);
    float4* dst = (float4*)Xs;
#pragma unroll
    for (int k = 0; k < 4; k++) dst[t + k * 512] = src[t + k * 512];
    __syncthreads();

    const int tr = t >> 5;      // warp id 0..15 -> 4 rows each
    const int td = t & 31;      // lane 0..31   -> 4 outputs each
    const int r0 = tr * 4;
    const int d0 = td * 4;

    ull acc[4][4];
#pragma unroll
    for (int i = 0; i < 4; i++)
#pragma unroll
        for (int j = 0; j < 4; j++) acc[i][j] = 0ull;

    const ulonglong2* Wv = (const ulonglong2*)W1p;
#pragma unroll 4
    for (int c2 = 0; c2 < 64; c2++) {
        ull x2[4];
#pragma unroll
        for (int i = 0; i < 4; i++)
            x2[i] = *(const ull*)&Xs[(r0 + i) * 128 + 2 * c2];   // uniform/warp
        ull w2[4];
        {
            ulonglong2 wa = Wv[c2 * 64 + td * 2];
            ulonglong2 wb = Wv[c2 * 64 + td * 2 + 1];
            w2[0] = wa.x; w2[1] = wa.y; w2[2] = wb.x; w2[3] = wb.y;
        }
#pragma unroll
        for (int i = 0; i < 4; i++)
#pragma unroll
            for (int j = 0; j < 4; j++)
                acc[i][j] = ffma2(x2[i], w2[j], acc[i][j]);
    }

    // Epilogue: h = relu(lo+hi + b1[d]); partial += h*W2[d]
    float part[4] = {0.f, 0.f, 0.f, 0.f};
#pragma unroll
    for (int j = 0; j < 4; j++) {
        float b1j = b1[d0 + j];
        float w2j = W2[d0 + j];
#pragma unroll
        for (int i = 0; i < 4; i++) {
            float lo, hi; upk2(acc[i][j], lo, hi);
            float h = fmaxf(lo + hi + b1j, 0.f);
            part[i] = fmaf(h, w2j, part[i]);
        }
    }
#pragma unroll
    for (int i = 0; i < 4; i++) red[r0 + i][td] = part[i];
    __syncthreads();

    if (t < 64) {
        float s = b2[0];
#pragma unroll
        for (int k = 0; k < 32; k++) s += red[t][k];
        g_buf[rowBase + t] = s;
    }
}

// =====================================================================
// Kernel B: argmin. grid = 256 = (b:8 | vc:8 | nc:4), 256 threads.
// Per block: 1024 vertices (4/thread, dup-packed f32x2), 512 points.
// Pass 1: cheap 3-FFMA2 screening score s~ = fma(z.., fma(y.., fma(x.., pp)))
//         tracking best-2 segments (of 32 points) per vertex.
// Pass 2: exact reference-rounding rescan of both segments:
//         dot = fma(nvz,pz, fma(nvy,py, nvx*px));  d2 = (vv + dot) + pp
//         (nv = -2*v exact scaling), first-occurrence tie-break.
// =====================================================================
__global__ void __launch_bounds__(256, 1)
kernelB(const float* __restrict__ verts, const float* __restrict__ gpos) {
    __shared__ float pts[512 * 8];   // per point: {x,x,y,y,z,z,pp,pp} = 16KB

    const int t  = threadIdx.x;
    const int nc = blockIdx.x & 3;
    const int vc = (blockIdx.x >> 2) & 7;
    const int b  = blockIdx.x >> 5;
    const int n0 = nc * 512;
    const int v0 = vc * 1024;

    for (int i = t; i < 512; i += 256) {
        const float* p = gpos + ((size_t)b * N_ + n0 + i) * 3;
        float x = p[0], y = p[1], z = p[2];
        float pn = __fmaf_rn(z, z, __fmaf_rn(y, y, __fmul_rn(x, x)));
        float4* d = (float4*)&pts[i * 8];
        d[0] = make_float4(x, x, y, y);
        d[1] = make_float4(z, z, pn, pn);
    }
    __syncthreads();

    // 4 vertices per thread: v0 + t, +256, +512, +768
    float nvx[4], nvy[4], nvz[4], vvq[4];
#pragma unroll
    for (int q = 0; q < 4; q++) {
        const float* vp = verts + ((size_t)b * V_ + v0 + q * 256 + t) * 3;
        float x = vp[0], y = vp[1], z = vp[2];
        nvx[q] = -2.f * x; nvy[q] = -2.f * y; nvz[q] = -2.f * z;
        vvq[q] = __fmaf_rn(z, z, __fmaf_rn(y, y, __fmul_rn(x, x)));
    }
    const ull X0 = pk2(nvx[0], nvx[1]), Y0 = pk2(nvy[0], nvy[1]), Z0 = pk2(nvz[0], nvz[1]);
    const ull X1 = pk2(nvx[2], nvx[3]), Y1 = pk2(nvy[2], nvy[3]), Z1 = pk2(nvz[2], nvz[3]);

    const float INF = __int_as_float(0x7f800000);
    float best[4] = {INF, INF, INF, INF};
    float sec [4] = {INF, INF, INF, INF};
    int   sg1 [4] = {0, 0, 0, 0};
    int   sg2 [4] = {0, 0, 0, 0};

    for (int s = 0; s < 16; s++) {               // 16 segments of 32 points
        float m0 = INF, m1 = INF, m2 = INF, m3 = INF;
        const ulonglong2* base = (const ulonglong2*)&pts[s * 32 * 8];
#pragma unroll 4
        for (int k = 0; k < 32; k++) {
            ulonglong2 a  = base[2 * k];         // {x,x},{y,y}
            ulonglong2 bq = base[2 * k + 1];     // {z,z},{pp,pp}
            ull s0 = ffma2(Z0, bq.x, ffma2(Y0, a.y, ffma2(X0, a.x, bq.y)));
            ull s1 = ffma2(Z1, bq.x, ffma2(Y1, a.y, ffma2(X1, a.x, bq.y)));
            float l0, h0, l1, h1;
            upk2(s0, l0, h0); upk2(s1, l1, h1);
            m0 = fminf(m0, l0); m1 = fminf(m1, h0);
            m2 = fminf(m2, l1); m3 = fminf(m3, h1);
        }
        float mq[4] = {m0, m1, m2, m3};
#pragma unroll
        for (int q = 0; q < 4; q++) {
            if (mq[q] < best[q]) {
                sec[q] = best[q]; sg2[q] = sg1[q];
                best[q] = mq[q];  sg1[q] = s;
            } else if (mq[q] < sec[q]) {
                sec[q] = mq[q]; sg2[q] = s;
            }
        }
    }

    // Pass 2: exact rescan of the two candidate segments (ascending order).
#pragma unroll 1
    for (int q = 0; q < 4; q++) {
        int lo = min(sg1[q], sg2[q]);
        int hi = max(sg1[q], sg2[q]);
        float cur = INF;
        int idx = 0;
#pragma unroll 1
        for (int pass = 0; pass < 2; pass++) {
            int sb = (pass == 0 ? lo : hi) * 32;
            if (pass == 1 && hi == lo) break;
#pragma unroll 1
            for (int k = 0; k < 32; k++) {
                const float* p = &pts[(sb + k) * 8];
                float s2 = __fmaf_rn(nvz[q], p[4],
                            __fmaf_rn(nvy[q], p[2],
                             __fmul_rn(nvx[q], p[0])));
                float d2 = __fadd_rn(__fadd_rn(vvq[q], s2), p[6]);
                if (d2 < cur) { cur = d2; idx = sb + k; }
            }
        }
        int o = b * V_ + v0 + q * 256 + t;
        cand_val[nc * (B_ * V_) + o] = cur;
        cand_idx[nc * (B_ * V_) + o] = n0 + idx;
    }
}

// =====================================================================
// Kernel C: combine 4 n-chunks (ascending -> first-occurrence ties) and
// gather g.
// =====================================================================
__global__ void kernelC(float* __restrict__ out) {
    int i = blockIdx.x * 256 + threadIdx.x;   // 0..65535
    float bv = cand_val[i];
    int   bi = cand_idx[i];
#pragma unroll
    for (int c = 1; c < 4; c++) {
        float v = cand_val[c * (B_ * V_) + i];
        int   x = cand_idx[c * (B_ * V_) + i];
        if (v < bv) { bv = v; bi = x; }
    }
    int b = i >> 13;
    out[i] = g_buf[b * N_ + bi];
}

// =====================================================================
extern "C" void kernel_launch(void* const* d_in, const int* in_sizes, int n_in,
                              void* d_out, int out_size) {
    const float* verts = (const float*)d_in[0];   // [8,8192,3]
    const float* gpos  = (const float*)d_in[1];   // [8,2048,3]
    const float* proc  = (const float*)d_in[2];   // [8,2048,128]
    const float* W1    = (const float*)d_in[3];   // [128,128]
    const float* b1    = (const float*)d_in[4];   // [128]
    const float* W2    = (const float*)d_in[5];   // [128,1]
    const float* b2    = (const float*)d_in[6];   // [1]
    float* out = (float*)d_out;                   // [8,8192,1]

    cudaFuncSetAttribute(kernelA, cudaFuncAttributeMaxDynamicSharedMemorySize,
                         64 * 128 * 4);

    kernelP<<<32, 256>>>(W1);
    kernelA<<<256, 512, 64 * 128 * 4>>>(proc, b1, W2, b2);
    kernelB<<<256, 256>>>(verts, gpos);
    kernelC<<<256, 256>>>(out);
}

// round 4
// speedup vs baseline: 1.3110x; 1.3110x over previous
#include <cuda_runtime.h>
#include <cstdint>

#define B_ 8
#define V_ 8192
#define N_ 2048
#define C_ 128

typedef unsigned long long ull;

// ---------- f32x2 helpers (sm_100+ packed fp32: SASS FFMA2) ----------
__device__ __forceinline__ ull pk2(float lo, float hi) {
    ull r; asm("mov.b64 %0, {%1, %2};" : "=l"(r) : "f"(lo), "f"(hi)); return r;
}
__device__ __forceinline__ void upk2(ull v, float& lo, float& hi) {
    asm("mov.b64 {%0, %1}, %2;" : "=f"(lo), "=f"(hi) : "l"(v));
}
__device__ __forceinline__ ull ffma2(ull a, ull b, ull c) {
    ull d; asm("fma.rn.f32x2 %0, %1, %2, %3;" : "=l"(d) : "l"(a), "l"(b), "l"(c)); return d;
}

// ---------- device scratch ----------
__device__ float g_buf[B_ * N_];    // g[b,n] = MLP(processed[b,n])
__device__ ull   W1p[64 * 128];     // packed W1: {W1[2c2][d], W1[2c2+1][d]}

// =====================================================================
// Kernel P: pack W1 row pairs for f32x2 consumption (runs once, tiny).
// =====================================================================
__global__ void kernelP(const float* __restrict__ W1) {
    int i = blockIdx.x * 256 + threadIdx.x;     // 8192 entries
    int c2 = i >> 7, d = i & 127;
    W1p[i] = pk2(W1[(2 * c2) * C_ + d], W1[(2 * c2 + 1) * C_ + d]);
}

// =====================================================================
// Kernel G: g table. 256 blocks x 64 rows, 512 threads.
// W1p staged in shared memory -> hot loop is pure LDS + FFMA2 (no
// global-latency exposure). Thread tile 4 rows x 4 outputs.
// smem: Ws 64KB + Xs 32KB = 96KB dynamic.
// =====================================================================
__global__ void __launch_bounds__(512, 1)
kernelG(const float* __restrict__ processed,
        const float* __restrict__ b1,
        const float* __restrict__ W2,
        const float* __restrict__ b2) {
    extern __shared__ char gsm[];
    ull*   Ws = (ull*)gsm;                         // [64*128] packed W1
    float* Xs = (float*)(gsm + 64 * 1024);         // [64][128]
    __shared__ float red[64][33];

    const int t = threadIdx.x;
    const int rowBase = blockIdx.x * 64;

    // Stage W1p -> smem (coalesced 16B copies)
    {
        const ulonglong2* src = (const ulonglong2*)W1p;
        ulonglong2* dst = (ulonglong2*)Ws;
#pragma unroll
        for (int k = 0; k < 8; k++) dst[t + k * 512] = src[t + k * 512];
    }
    // Stage X rows -> smem
    {
        const float4* src = (const float4*)(processed + (size_t)rowBase * C_);
        float4* dst = (float4*)Xs;
#pragma unroll
        for (int k = 0; k < 4; k++) dst[t + k * 512] = src[t + k * 512];
    }
    __syncthreads();

    const int tr = t >> 5;      // warp id 0..15 -> 4 rows each
    const int td = t & 31;      // lane 0..31   -> 4 outputs each
    const int r0 = tr * 4;
    const int d0 = td * 4;

    ull acc[4][4];
#pragma unroll
    for (int i = 0; i < 4; i++)
#pragma unroll
        for (int j = 0; j < 4; j++) acc[i][j] = 0ull;

    const ulonglong2* Wsv = (const ulonglong2*)Ws;
#pragma unroll 8
    for (int c2 = 0; c2 < 64; c2++) {
        ull x2[4];
#pragma unroll
        for (int i = 0; i < 4; i++)
            x2[i] = *(const ull*)&Xs[(r0 + i) * 128 + 2 * c2];   // warp-broadcast
        ull w2[4];
        {
            ulonglong2 wa = Wsv[c2 * 64 + td * 2];
            ulonglong2 wb = Wsv[c2 * 64 + td * 2 + 1];
            w2[0] = wa.x; w2[1] = wa.y; w2[2] = wb.x; w2[3] = wb.y;
        }
#pragma unroll
        for (int i = 0; i < 4; i++)
#pragma unroll
            for (int j = 0; j < 4; j++)
                acc[i][j] = ffma2(x2[i], w2[j], acc[i][j]);
    }

    // Epilogue: h = relu(lo+hi + b1[d]); partial += h*W2[d]
    float part[4] = {0.f, 0.f, 0.f, 0.f};
#pragma unroll
    for (int j = 0; j < 4; j++) {
        float b1j = b1[d0 + j];
        float w2j = W2[d0 + j];
#pragma unroll
        for (int i = 0; i < 4; i++) {
            float lo, hi; upk2(acc[i][j], lo, hi);
            float h = fmaxf(lo + hi + b1j, 0.f);
            part[i] = fmaf(h, w2j, part[i]);
        }
    }
#pragma unroll
    for (int i = 0; i < 4; i++) red[r0 + i][td] = part[i];
    __syncthreads();

    if (t < 64) {
        float s = b2[0];
#pragma unroll
        for (int k = 0; k < 32; k++) s += red[t][k];
        g_buf[rowBase + t] = s;
    }
}

// =====================================================================
// Kernel BC: fused argmin + gather. grid = 128 = (b:8 | vc:16),
// 256 threads, 2 vertices/thread (one f32x2 pair), FULL n per block
// (2048 points staged in 64KB smem) -> single wave, no cand arrays.
//
// Pass 1: screen score s~ = fma(Z,z, fma(Y,y, fma(X,x, pp))) packed,
//         track best-2 segments (of 32 points) per vertex.
// Pass 2: exact reference-rounding rescan of both segments:
//         dot' = fma(nvz,pz, fma(nvy,py, nvx*px))  (nv = -2v, exact)
//         d2   = (vv + dot') + pp, first-occurrence tie-break.
// Then out = g_buf[b, argmin] directly.
// =====================================================================
__global__ void __launch_bounds__(256, 1)
kernelBC(const float* __restrict__ verts, const float* __restrict__ gpos,
         float* __restrict__ out) {
    extern __shared__ float pts[];   // [2048][8] {x,x,y,y,z,z,pp,pp} = 64KB

    const int t  = threadIdx.x;
    const int vc = blockIdx.x & 15;
    const int b  = blockIdx.x >> 4;
    const int v0 = vc * 512;

    for (int i = t; i < N_; i += 256) {
        const float* p = gpos + ((size_t)b * N_ + i) * 3;
        float x = p[0], y = p[1], z = p[2];
        float pn = __fmaf_rn(z, z, __fmaf_rn(y, y, __fmul_rn(x, x)));
        float4* d = (float4*)&pts[i * 8];
        d[0] = make_float4(x, x, y, y);
        d[1] = make_float4(z, z, pn, pn);
    }
    __syncthreads();

    // 2 vertices per thread: v0 + t, v0 + t + 256
    float nvx[2], nvy[2], nvz[2], vvq[2];
#pragma unroll
    for (int q = 0; q < 2; q++) {
        const float* vp = verts + ((size_t)b * V_ + v0 + q * 256 + t) * 3;
        float x = vp[0], y = vp[1], z = vp[2];
        nvx[q] = -2.f * x; nvy[q] = -2.f * y; nvz[q] = -2.f * z;
        vvq[q] = __fmaf_rn(z, z, __fmaf_rn(y, y, __fmul_rn(x, x)));
    }
    const ull X = pk2(nvx[0], nvx[1]);
    const ull Y = pk2(nvy[0], nvy[1]);
    const ull Z = pk2(nvz[0], nvz[1]);

    const float INF = __int_as_float(0x7f800000);
    float best0 = INF, best1 = INF, sec0 = INF, sec1 = INF;
    int sgA0 = 0, sgA1 = 0, sgB0 = 0, sgB1 = 0;

    for (int s = 0; s < 64; s++) {               // 64 segments of 32 points
        float m0 = INF, m1 = INF;
        const ulonglong2* base = (const ulonglong2*)&pts[s * 32 * 8];
#pragma unroll 8
        for (int k = 0; k < 32; k++) {
            ulonglong2 a  = base[2 * k];         // {x,x},{y,y}
            ulonglong2 bq = base[2 * k + 1];     // {z,z},{pp,pp}
            ull sc = ffma2(Z, bq.x, ffma2(Y, a.y, ffma2(X, a.x, bq.y)));
            float lo, hi; upk2(sc, lo, hi);
            m0 = fminf(m0, lo); m1 = fminf(m1, hi);
        }
        if (m0 < best0) { sec0 = best0; sgB0 = sgA0; best0 = m0; sgA0 = s; }
        else if (m0 < sec0) { sec0 = m0; sgB0 = s; }
        if (m1 < best1) { sec1 = best1; sgB1 = sgA1; best1 = m1; sgA1 = s; }
        else if (m1 < sec1) { sec1 = m1; sgB1 = s; }
    }

    int sga[2] = {sgA0, sgA1};
    int sgb[2] = {sgB0, sgB1};

#pragma unroll 1
    for (int q = 0; q < 2; q++) {
        int lo = min(sga[q], sgb[q]);
        int hi = max(sga[q], sgb[q]);
        float cur = INF;
        int idx = 0;
#pragma unroll 1
        for (int pass = 0; pass < 2; pass++) {
            if (pass == 1 && hi == lo) break;
            int sb = (pass == 0 ? lo : hi) * 32;
#pragma unroll 1
            for (int k = 0; k < 32; k++) {
                const float* p = &pts[(sb + k) * 8];
                float s2 = __fmaf_rn(nvz[q], p[4],
                            __fmaf_rn(nvy[q], p[2],
                             __fmul_rn(nvx[q], p[0])));
                float d2 = __fadd_rn(__fadd_rn(vvq[q], s2), p[6]);
                if (d2 < cur) { cur = d2; idx = sb + k; }
            }
        }
        out[b * V_ + v0 + q * 256 + t] = g_buf[b * N_ + idx];
    }
}

// =====================================================================
extern "C" void kernel_launch(void* const* d_in, const int* in_sizes, int n_in,
                              void* d_out, int out_size) {
    const float* verts = (const float*)d_in[0];   // [8,8192,3]
    const float* gpos  = (const float*)d_in[1];   // [8,2048,3]
    const float* proc  = (const float*)d_in[2];   // [8,2048,128]
    const float* W1    = (const float*)d_in[3];   // [128,128]
    const float* b1    = (const float*)d_in[4];   // [128]
    const float* W2    = (const float*)d_in[5];   // [128,1]
    const float* b2    = (const float*)d_in[6];   // [1]
    float* out = (float*)d_out;                   // [8,8192,1]

    cudaFuncSetAttribute(kernelG, cudaFuncAttributeMaxDynamicSharedMemorySize,
                         96 * 1024);
    cudaFuncSetAttribute(kernelBC, cudaFuncAttributeMaxDynamicSharedMemorySize,
                         64 * 1024);

    kernelP<<<32, 256>>>(W1);
    kernelG<<<256, 512, 96 * 1024>>>(proc, b1, W2, b2);
    kernelBC<<<128, 256, 64 * 1024>>>(verts, gpos, out);
}

// round 5
// speedup vs baseline: 1.3753x; 1.0490x over previous
#include <cuda_runtime.h>
#include <cstdint>

#define B_ 8
#define V_ 8192
#define N_ 2048
#define C_ 128
#define GRID_ 128
#define THR_ 512

typedef unsigned long long ull;

// ---------- f32x2 helpers (sm_100+ packed fp32: SASS FFMA2) ----------
__device__ __forceinline__ ull pk2(float lo, float hi) {
    ull r; asm("mov.b64 %0, {%1, %2};" : "=l"(r) : "f"(lo), "f"(hi)); return r;
}
__device__ __forceinline__ void upk2(ull v, float& lo, float& hi) {
    asm("mov.b64 {%0, %1}, %2;" : "=f"(lo), "=f"(hi) : "l"(v));
}
__device__ __forceinline__ ull ffma2(ull a, ull b, ull c) {
    ull d; asm("fma.rn.f32x2 %0, %1, %2, %3;" : "=l"(d) : "l"(a), "l"(b), "l"(c)); return d;
}

// ---------- device scratch ----------
__device__ float g_buf[B_ * N_];          // g[b,n] = MLP(processed[b,n])
__device__ unsigned int bar_arrive;       // software grid barrier (self-resetting)
__device__ unsigned int bar_done;

// =====================================================================
// ONE persistent kernel. grid=128 blocks (1/SM, all resident), 512 thr.
// Phase 1: g table (each block: 128 rows, two 64-row subtiles; W1
//          packed into smem once). Thread tile 4 rows x 4 outputs.
// Grid barrier (atomic arrive + spin, reset by last-exiting block).
// Phase 2: argmin+gather. Block = (b:8 | vc:16) -> 512 vertices,
//          full N=2048 points pair-packed in smem (16B/point).
//          Screen best-2 segments w/ 3xFFMA2, exact rescan, gather g.
// =====================================================================
__global__ void __launch_bounds__(THR_, 1)
kernelFused(const float* __restrict__ verts,
            const float* __restrict__ gpos,
            const float* __restrict__ processed,
            const float* __restrict__ W1,
            const float* __restrict__ b1,
            const float* __restrict__ W2,
            const float* __restrict__ b2,
            float* __restrict__ out) {
    extern __shared__ char sm[];
    ull*   Ws  = (ull*)sm;                    // phase1: packed W1, 64KB
    float* Xs  = (float*)(sm + 65536);        // phase1: X tile, 32KB
    float* pts = (float*)sm;                  // phase2: pair-packed points, 32KB
    __shared__ float red[64][33];

    const int t   = threadIdx.x;
    const int bid = blockIdx.x;

    // ---------------- Phase 1: g table ----------------
    // Pack W1 into smem: Ws[c2*128+d] = {W1[2c2][d], W1[2c2+1][d]}
#pragma unroll
    for (int k = 0; k < 16; k++) {
        int i = t + k * THR_;                 // 0..8191
        int c2 = i >> 7, d = i & 127;
        Ws[i] = pk2(W1[(2 * c2) * C_ + d], W1[(2 * c2 + 1) * C_ + d]);
    }

    const int tr = t >> 5;        // warp 0..15 -> 4 rows each
    const int td = t & 31;        // lane       -> 4 outputs each
    const int r0 = tr * 4;
    const int d0 = td * 4;
    const ulonglong2* Wsv = (const ulonglong2*)Ws;

#pragma unroll 1
    for (int h = 0; h < 2; h++) {
        const int rb = bid * 128 + h * 64;    // 64 global rows this subtile

        const float4* src = (const float4*)(processed + (size_t)rb * C_);
        float4* dst = (float4*)Xs;
#pragma unroll
        for (int k = 0; k < 4; k++) dst[t + k * THR_] = src[t + k * THR_];
        __syncthreads();

        ull acc[4][4];
#pragma unroll
        for (int i = 0; i < 4; i++)
#pragma unroll
            for (int j = 0; j < 4; j++) acc[i][j] = 0ull;

#pragma unroll 8
        for (int c2 = 0; c2 < 64; c2++) {
            ull x2[4];
#pragma unroll
            for (int i = 0; i < 4; i++)
                x2[i] = *(const ull*)&Xs[(r0 + i) * 128 + 2 * c2];  // warp-bcast
            ull w2[4];
            {
                ulonglong2 wa = Wsv[c2 * 64 + td * 2];
                ulonglong2 wb = Wsv[c2 * 64 + td * 2 + 1];
                w2[0] = wa.x; w2[1] = wa.y; w2[2] = wb.x; w2[3] = wb.y;
            }
#pragma unroll
            for (int i = 0; i < 4; i++)
#pragma unroll
                for (int j = 0; j < 4; j++)
                    acc[i][j] = ffma2(x2[i], w2[j], acc[i][j]);
        }

        float part[4] = {0.f, 0.f, 0.f, 0.f};
#pragma unroll
        for (int j = 0; j < 4; j++) {
            float b1j = b1[d0 + j];
            float w2j = W2[d0 + j];
#pragma unroll
            for (int i = 0; i < 4; i++) {
                float lo, hi; upk2(acc[i][j], lo, hi);
                float hv = fmaxf(lo + hi + b1j, 0.f);
                part[i] = fmaf(hv, w2j, part[i]);
            }
        }
#pragma unroll
        for (int i = 0; i < 4; i++) red[r0 + i][td] = part[i];
        __syncthreads();

        if (t < 64) {
            float s = b2[0];
#pragma unroll
            for (int k = 0; k < 32; k++) s += red[t][k];
            g_buf[rb + t] = s;
        }
        __syncthreads();
    }

    // ---------------- Grid barrier ----------------
    __threadfence();                // release g_buf writes (all threads)
    __syncthreads();
    if (t == 0) {
        atomicAdd(&bar_arrive, 1u);
        while (*(volatile unsigned int*)&bar_arrive < GRID_) __nanosleep(64);
    }
    __syncthreads();
    __threadfence();                // acquire before reading g_buf

    // ---------------- Phase 2: argmin + gather ----------------
    const int vc = bid & 15;
    const int b  = bid >> 4;
    const int v0 = vc * 512;

    // Pair-packed point tile: pair j -> {x0,x1, y0,y1, z0,z1, pp0,pp1}
    for (int j = t; j < N_ / 2; j += THR_) {
        const float* p0 = gpos + ((size_t)b * N_ + 2 * j) * 3;
        float x0 = p0[0], y0 = p0[1], z0 = p0[2];
        float x1 = p0[3], y1 = p0[4], z1 = p0[5];
        float pp0 = __fmaf_rn(z0, z0, __fmaf_rn(y0, y0, __fmul_rn(x0, x0)));
        float pp1 = __fmaf_rn(z1, z1, __fmaf_rn(y1, y1, __fmul_rn(x1, x1)));
        float4* d = (float4*)&pts[j * 8];
        d[0] = make_float4(x0, x1, y0, y1);
        d[1] = make_float4(z0, z1, pp0, pp1);
    }
    __syncthreads();

    // One vertex per thread
    const float* vp = verts + ((size_t)b * V_ + v0 + t) * 3;
    float vx = vp[0], vy = vp[1], vz = vp[2];
    float nvx = -2.f * vx, nvy = -2.f * vy, nvz = -2.f * vz;
    float vv = __fmaf_rn(vz, vz, __fmaf_rn(vy, vy, __fmul_rn(vx, vx)));
    const ull Xp = pk2(nvx, nvx), Yp = pk2(nvy, nvy), Zp = pk2(nvz, nvz);

    const float INF = __int_as_float(0x7f800000);
    float best = INF, sec = INF;
    int sgA = 0, sgB = 0;

    // 64 segments of 32 points (16 pairs each)
    for (int s = 0; s < 64; s++) {
        float m = INF;
        const ulonglong2* base = (const ulonglong2*)&pts[s * 128];
#pragma unroll 8
        for (int k = 0; k < 16; k++) {
            ulonglong2 a  = base[2 * k];       // {x0,x1},{y0,y1}
            ulonglong2 bq = base[2 * k + 1];   // {z0,z1},{pp0,pp1}
            ull sc = ffma2(Zp, bq.x, ffma2(Yp, a.y, ffma2(Xp, a.x, bq.y)));
            float lo, hi; upk2(sc, lo, hi);
            m = fminf(m, lo); m = fminf(m, hi);
        }
        if (m < best) { sec = best; sgB = sgA; best = m; sgA = s; }
        else if (m < sec) { sec = m; sgB = s; }
    }

    // Exact rescan of the two candidate segments, ascending (first-occurrence)
    {
        int lo = min(sgA, sgB);
        int hi = max(sgA, sgB);
        float cur = INF;
        int idx = 0;
#pragma unroll 1
        for (int pass = 0; pass < 2; pass++) {
            if (pass == 1 && hi == lo) break;
            int sb = (pass == 0 ? lo : hi) * 32;
#pragma unroll 1
            for (int i = 0; i < 32; i++) {
                int p = sb + i;
                const float* q = &pts[(p >> 1) * 8 + (p & 1)];
                float s2 = __fmaf_rn(nvz, q[4],
                            __fmaf_rn(nvy, q[2],
                             __fmul_rn(nvx, q[0])));
                float d2 = __fadd_rn(__fadd_rn(vv, s2), q[6]);
                if (d2 < cur) { cur = d2; idx = p; }
            }
        }
        out[b * V_ + v0 + t] = g_buf[b * N_ + idx];
    }

    // ---------------- Exit: reset barrier (last block) ----------------
    __syncthreads();
    if (t == 0) {
        unsigned int r = atomicAdd(&bar_done, 1u);
        if (r == GRID_ - 1) {                 // strictly after ALL blocks' work
            atomicExch(&bar_arrive, 0u);
            atomicExch(&bar_done, 0u);
        }
    }
}

// =====================================================================
extern "C" void kernel_launch(void* const* d_in, const int* in_sizes, int n_in,
                              void* d_out, int out_size) {
    const float* verts = (const float*)d_in[0];   // [8,8192,3]
    const float* gpos  = (const float*)d_in[1];   // [8,2048,3]
    const float* proc  = (const float*)d_in[2];   // [8,2048,128]
    const float* W1    = (const float*)d_in[3];   // [128,128]
    const float* b1    = (const float*)d_in[4];   // [128]
    const float* W2    = (const float*)d_in[5];   // [128,1]
    const float* b2    = (const float*)d_in[6];   // [1]
    float* out = (float*)d_out;                   // [8,8192,1]

    cudaFuncSetAttribute(kernelFused, cudaFuncAttributeMaxDynamicSharedMemorySize,
                         96 * 1024);
    kernelFused<<<GRID_, THR_, 96 * 1024>>>(verts, gpos, proc, W1, b1, W2, b2, out);
}